// round 7
// baseline (speedup 1.0000x reference)
#include <cuda_runtime.h>
#include <stdint.h>

// ---------------------------------------------------------------------------
// GPRNet: out = sum_k temp[k] * A_hat^k (MLP(x)@W_fc) + b_fc  (scalar per node)
// TWO launches total:
//   k_mlp : per-node MLP -> g_s, zero g_deg, reset grid barrier
//   k_all : persistent (1 block/SM, 1024 thr): histogram -> scan -> scatter
//           (CSC counting sort) -> K propagation hops, all separated by an
//           IVALL grid barrier (gpu-scope __threadfence emits CCTL.IVALL, so
//           plain L1-cached __ldg gathers are coherent across phases/hops —
//           validated in R6, rel_err 1.79e-7).
// ---------------------------------------------------------------------------

#define MAXN   100352
#define MAXE   3276800
#define NBLK   256
#define PTHR   1024
#define MAXB   160          // max persistent blocks (#SMs <= 160)

__device__ int      g_deg[MAXN];
__device__ int      g_off[MAXN + 1];
__device__ int      g_cursor[MAXN];
__device__ int      g_blkTot[MAXB];
__device__ int      g_srow[MAXE];
__device__ float    g_dinv[MAXN];
__device__ float    g_s[MAXN];
__device__ float    g_hidden[MAXN];
__device__ float    g_curwA[MAXN];
__device__ float    g_curwB[MAXN];
__device__ unsigned g_barrier;

// ---- per-node MLP (+ zero histogram, + barrier reset) -----------------------
__global__ void __launch_bounds__(NBLK) k_mlp(
    const float* __restrict__ x,
    const float* __restrict__ W1, const float* __restrict__ b1,
    const float* __restrict__ W2, const float* __restrict__ b2,
    const float* __restrict__ Wfc, int N)
{
    __shared__ float sW1[32], sB1[32], sB2[64], sWfc[64];
    __shared__ __align__(16) float sW2[2048];

    for (int t = threadIdx.x; t < 2048; t += blockDim.x) sW2[t] = W2[t];
    if (threadIdx.x < 32) { sW1[threadIdx.x] = W1[threadIdx.x]; sB1[threadIdx.x] = b1[threadIdx.x]; }
    if (threadIdx.x < 64) { sB2[threadIdx.x] = b2[threadIdx.x]; sWfc[threadIdx.x] = Wfc[threadIdx.x]; }
    __syncthreads();

    int i = blockIdx.x * blockDim.x + threadIdx.x;
    if (i >= N) return;
    if (i == 0) g_barrier = 0;          // reset persistent-kernel barrier

    float xv = x[i];
    float acc[64];
#pragma unroll
    for (int j = 0; j < 64; j++) acc[j] = sB2[j];
#pragma unroll
    for (int j1 = 0; j1 < 32; j1++) {
        float h = fmaxf(fmaf(xv, sW1[j1], sB1[j1]), 0.0f);
        const float4* w2r = reinterpret_cast<const float4*>(&sW2[j1 * 64]);
#pragma unroll
        for (int j = 0; j < 16; j++) {
            float4 w = w2r[j];
            acc[4*j+0] = fmaf(h, w.x, acc[4*j+0]);
            acc[4*j+1] = fmaf(h, w.y, acc[4*j+1]);
            acc[4*j+2] = fmaf(h, w.z, acc[4*j+2]);
            acc[4*j+3] = fmaf(h, w.w, acc[4*j+3]);
        }
    }
    float s = 0.0f;
#pragma unroll
    for (int j = 0; j < 64; j++) s = fmaf(fmaxf(acc[j], 0.0f), sWfc[j], s);

    g_s[i]   = s;
    g_deg[i] = 0;
}

// ---- grid barrier (release + IVALL acquire), 1 block/SM => co-resident ------
__device__ __forceinline__ void gridbar(unsigned& target)
{
    __syncthreads();
    if (threadIdx.x == 0) {
        __threadfence();                      // release (+CCTL.IVALL)
        atomicAdd(&g_barrier, 1u);
        target += gridDim.x;
        while (*(volatile unsigned*)&g_barrier < target)
            __nanosleep(64);
        __threadfence();                      // acquire (+CCTL.IVALL)
    }
    __syncthreads();
}

// ---- persistent everything: hist -> scan -> scatter -> K hops ---------------
__global__ void __launch_bounds__(PTHR, 1) k_all(
    const int* __restrict__ row, const int* __restrict__ col,
    const float* __restrict__ temp, const float* __restrict__ bfc,
    float* __restrict__ out, int N, int E, int K)
{
    const int tid  = threadIdx.x;
    const int nB   = gridDim.x;
    const int gthr = nB * PTHR;
    const int gtid = blockIdx.x * PTHR + tid;
    unsigned  target = 0;

    const bool v4  = ((E & 3) == 0);
    const int  E4  = E >> 2;

    // ---------- Phase A: histogram of col ----------
    if (v4) {
        const int4* c4p = reinterpret_cast<const int4*>(col);
        for (int t = gtid; t < E4; t += gthr) {
            int4 c = c4p[t];
            atomicAdd(&g_deg[c.x], 1);
            atomicAdd(&g_deg[c.y], 1);
            atomicAdd(&g_deg[c.z], 1);
            atomicAdd(&g_deg[c.w], 1);
        }
    } else {
        for (int e = gtid; e < E; e += gthr)
            atomicAdd(&g_deg[col[e]], 1);
    }
    gridbar(target);

    // ---------- Phase B: per-block local scan of contiguous chunk ----------
    __shared__ int sh[PTHR];
    __shared__ int shb[MAXB];
    const int CH    = (N + nB - 1) / nB;       // <= PTHR by construction
    const int base0 = blockIdx.x * CH;
    const int i     = base0 + tid;

    int v = (tid < CH && i < N) ? g_deg[i] : 0;
    sh[tid] = v;
    __syncthreads();
#pragma unroll
    for (int d = 1; d < PTHR; d <<= 1) {
        int t2 = (tid >= d) ? sh[tid - d] : 0;
        __syncthreads();
        sh[tid] += t2;
        __syncthreads();
    }
    int incl = sh[tid];
    if (tid < CH && i < N) g_off[i] = incl - v;           // local exclusive
    {
        int nvalid = N - base0;
        if (nvalid > CH) nvalid = CH;
        if (nvalid < 0)  nvalid = 0;
        if (tid == 0) g_blkTot[blockIdx.x] = nvalid ? sh[nvalid - 1] : 0;
    }
    gridbar(target);

    // ---------- Phase B3: cross-block base + finalize (dinv/hidden/seed) -----
    if (tid < nB) shb[tid] = g_blkTot[tid];
    __syncthreads();
    if (tid == 0) {
        int run = 0;
        for (int j = 0; j < nB; j++) { int t = shb[j]; shb[j] = run; run += t; }
    }
    __syncthreads();
    const int myBase = shb[blockIdx.x];
    if (tid < CH && i < N) {
        int val = g_off[i] + myBase;
        g_off[i]    = val;
        g_cursor[i] = val;
        float d = rsqrtf((float)(g_deg[i] + 1));          // +1 self-loop
        g_dinv[i]   = d;
        float s     = g_s[i];
        g_hidden[i] = __ldg(&temp[0]) * s;
        g_curwA[i]  = d * s;
    }
    if (gtid == 0) g_off[N] = E;
    gridbar(target);

    // ---------- Phase C: scatter edges into CSC order ----------
    if (v4) {
        const int4* r4p = reinterpret_cast<const int4*>(row);
        const int4* c4p = reinterpret_cast<const int4*>(col);
        for (int t = gtid; t < E4; t += gthr) {
            int4 r = r4p[t];
            int4 c = c4p[t];
            g_srow[atomicAdd(&g_cursor[c.x], 1)] = r.x;
            g_srow[atomicAdd(&g_cursor[c.y], 1)] = r.y;
            g_srow[atomicAdd(&g_cursor[c.z], 1)] = r.z;
            g_srow[atomicAdd(&g_cursor[c.w], 1)] = r.w;
        }
    } else {
        for (int e = gtid; e < E; e += gthr)
            g_srow[atomicAdd(&g_cursor[col[e]], 1)] = row[e];
    }
    gridbar(target);

    // ---------- Phase D: K propagation hops ----------
    const int warpsPerBlk = PTHR / 32;
    const int nwarps = nB * warpsPerBlk;
    const int gw     = blockIdx.x * warpsPerBlk + (tid >> 5);
    const int lane   = tid & 31;
    const float bias = __ldg(&bfc[0]);

    const int npw    = (N + nwarps - 1) / nwarps;
    const int nodeLo = gw * npw;
    const int nodeHi = (nodeLo + npw < N) ? (nodeLo + npw) : N;

    const float* curwIn  = g_curwA;
    float*       curwOut = g_curwB;

    for (int k = 1; k <= K; k++) {
        const float gamma = __ldg(&temp[k]);
        const bool  last  = (k == K);

        for (int b = nodeLo; b < nodeHi; b += 32) {
            int  cnt = nodeHi - b; if (cnt > 32) cnt = 32;
            int  idx = b + lane;
            bool act = lane < cnt;

            int   myStart = act ? __ldg(&g_off[idx])     : 0;
            int   myNext  = act ? __ldg(&g_off[idx + 1]) : 0;
            float myDinv  = act ? g_dinv[idx]            : 0.0f;
            float myHid   = act ? g_hidden[idx]          : 0.0f;
            float mySelf  = act ? curwIn[idx]            : 0.0f;
            float mySum   = 0.0f;

            for (int j = 0; j < cnt; j++) {
                int s = __shfl_sync(0xFFFFFFFFu, myStart, j);
                int e = __shfl_sync(0xFFFFFFFFu, myNext,  j);

                float sum = 0.0f;
                for (int t = s + lane; t < e; t += 32)
                    sum += __ldg(&curwIn[__ldg(&g_srow[t])]);   // L1-cached gather

#pragma unroll
                for (int d = 16; d > 0; d >>= 1)
                    sum += __shfl_xor_sync(0xFFFFFFFFu, sum, d);

                if (lane == j) mySum = sum;
            }

            float cur = myDinv * (mySelf + mySum);
            float h   = fmaf(gamma, cur, myHid);
            if (act) {
                if (last) {
                    out[idx] = h + bias;
                } else {
                    g_hidden[idx] = h;
                    curwOut[idx]  = myDinv * cur;
                }
            }
        }

        if (!last) {
            gridbar(target);
            float* t2 = curwOut;
            curwOut   = const_cast<float*>(curwIn);
            curwIn    = t2;
        }
    }
}

// ---------------------------------------------------------------------------
extern "C" void kernel_launch(void* const* d_in, const int* in_sizes, int n_in,
                              void* d_out, int out_size)
{
    const float* x    = (const float*)d_in[0];
    const int*   ei   = (const int*)  d_in[1];
    const float* W1   = (const float*)d_in[2];
    const float* b1   = (const float*)d_in[3];
    const float* W2   = (const float*)d_in[4];
    const float* b2   = (const float*)d_in[5];
    const float* temp = (const float*)d_in[6];
    const float* Wfc  = (const float*)d_in[7];
    const float* bfc  = (const float*)d_in[8];
    float*       out  = (float*)d_out;

    int N = in_sizes[0];
    int E = in_sizes[1] / 2;
    int K = in_sizes[6] - 1;

    const int* row = ei;
    const int* col = ei + E;

    int nb = (N + NBLK - 1) / NBLK;

    // one block per SM -> persistent grid always fully resident (no deadlock)
    int dev = 0, sms = 0;
    cudaGetDevice(&dev);
    cudaDeviceGetAttribute(&sms, cudaDevAttrMultiProcessorCount, dev);
    if (sms <= 0) sms = 148;
    if (sms > MAXB) sms = MAXB;
    // scan chunk must fit one block
    while ((N + sms - 1) / sms > PTHR) sms++;   // never triggers for N<=151k

    k_mlp<<<nb, NBLK>>>(x, W1, b1, W2, b2, Wfc, N);
    k_all<<<sms, PTHR>>>(row, col, temp, bfc, out, N, E, K);
}

// round 8
// speedup vs baseline: 1.2197x; 1.2197x over previous
#include <cuda_runtime.h>
#include <stdint.h>

// ---------------------------------------------------------------------------
// GPRNet: out = sum_k temp[k] * A_hat^k (MLP(x)@W_fc) + b_fc  (scalar per node)
// R6 structure (separate setup launches, persistent hop kernel with IVALL
// grid barrier) + hop occupancy doubled: 2 blocks x 1024 thr per SM
// (__launch_bounds__(1024,2) caps regs at 32 -> co-residency guaranteed),
// 64 warps/SM to cover gather latency (R7 ncu: occ=50%, issue=17.7%,
// L2=40%, DRAM=1% -> latency-bound).
// ---------------------------------------------------------------------------

#define MAXN   100352
#define MAXE   3276800
#define NBLK   256
#define EBLK   256
#define SCANB  1024
#define MAXSB  128
#define PTHR   1024

__device__ int      g_deg[MAXN];
__device__ int      g_off[MAXN + 1];
__device__ int      g_cursor[MAXN];
__device__ int      g_blk[MAXSB];
__device__ int      g_srow[MAXE];
__device__ float    g_dinv[MAXN];
__device__ float    g_s[MAXN];
__device__ float    g_hidden[MAXN];
__device__ float    g_curwA[MAXN];
__device__ float    g_curwB[MAXN];
__device__ unsigned g_barrier;

// ---- per-node MLP (+ zero histogram, + barrier reset) -----------------------
__global__ void __launch_bounds__(NBLK) k_mlp(
    const float* __restrict__ x,
    const float* __restrict__ W1, const float* __restrict__ b1,
    const float* __restrict__ W2, const float* __restrict__ b2,
    const float* __restrict__ Wfc, int N)
{
    __shared__ float sW1[32], sB1[32], sB2[64], sWfc[64];
    __shared__ __align__(16) float sW2[2048];

    for (int t = threadIdx.x; t < 2048; t += blockDim.x) sW2[t] = W2[t];
    if (threadIdx.x < 32) { sW1[threadIdx.x] = W1[threadIdx.x]; sB1[threadIdx.x] = b1[threadIdx.x]; }
    if (threadIdx.x < 64) { sB2[threadIdx.x] = b2[threadIdx.x]; sWfc[threadIdx.x] = Wfc[threadIdx.x]; }
    __syncthreads();

    int i = blockIdx.x * blockDim.x + threadIdx.x;
    if (i >= N) return;
    if (i == 0) g_barrier = 0;          // reset persistent-kernel barrier

    float xv = x[i];
    float acc[64];
#pragma unroll
    for (int j = 0; j < 64; j++) acc[j] = sB2[j];
#pragma unroll
    for (int j1 = 0; j1 < 32; j1++) {
        float h = fmaxf(fmaf(xv, sW1[j1], sB1[j1]), 0.0f);
        const float4* w2r = reinterpret_cast<const float4*>(&sW2[j1 * 64]);
#pragma unroll
        for (int j = 0; j < 16; j++) {
            float4 w = w2r[j];
            acc[4*j+0] = fmaf(h, w.x, acc[4*j+0]);
            acc[4*j+1] = fmaf(h, w.y, acc[4*j+1]);
            acc[4*j+2] = fmaf(h, w.z, acc[4*j+2]);
            acc[4*j+3] = fmaf(h, w.w, acc[4*j+3]);
        }
    }
    float s = 0.0f;
#pragma unroll
    for (int j = 0; j < 64; j++) s = fmaf(fmaxf(acc[j], 0.0f), sWfc[j], s);

    g_s[i]   = s;
    g_deg[i] = 0;
}

// ---- histogram of col --------------------------------------------------------
__global__ void __launch_bounds__(EBLK) k_hist_vec(const int* __restrict__ col, int E4, int rem)
{
    int t = blockIdx.x * blockDim.x + threadIdx.x;
    if (t < E4) {
        int4 c4 = reinterpret_cast<const int4*>(col)[t];
        atomicAdd(&g_deg[c4.x], 1);
        atomicAdd(&g_deg[c4.y], 1);
        atomicAdd(&g_deg[c4.z], 1);
        atomicAdd(&g_deg[c4.w], 1);
    } else if (t - E4 < rem) {
        atomicAdd(&g_deg[col[4 * E4 + (t - E4)]], 1);
    }
}
__global__ void __launch_bounds__(EBLK) k_hist_sca(const int* __restrict__ col, int E)
{
    int e = blockIdx.x * blockDim.x + threadIdx.x;
    if (e < E) atomicAdd(&g_deg[col[e]], 1);
}

// ---- 3-kernel exclusive scan of g_deg -> g_off ------------------------------
__global__ void __launch_bounds__(SCANB) k_scan1(int N)
{
    __shared__ int sh[SCANB];
    int i = blockIdx.x * SCANB + threadIdx.x;
    int v = (i < N) ? g_deg[i] : 0;
    sh[threadIdx.x] = v;
    __syncthreads();
#pragma unroll
    for (int d = 1; d < SCANB; d <<= 1) {
        int t = (threadIdx.x >= d) ? sh[threadIdx.x - d] : 0;
        __syncthreads();
        sh[threadIdx.x] += t;
        __syncthreads();
    }
    int incl = sh[threadIdx.x];
    if (i < N) g_off[i] = incl - v;
    if (threadIdx.x == SCANB - 1) g_blk[blockIdx.x] = incl;
}

__global__ void __launch_bounds__(MAXSB) k_scan2(int nb)
{
    __shared__ int sh[MAXSB];
    int v = (threadIdx.x < nb) ? g_blk[threadIdx.x] : 0;
    sh[threadIdx.x] = v;
    __syncthreads();
#pragma unroll
    for (int d = 1; d < MAXSB; d <<= 1) {
        int t = (threadIdx.x >= d) ? sh[threadIdx.x - d] : 0;
        __syncthreads();
        sh[threadIdx.x] += t;
        __syncthreads();
    }
    if (threadIdx.x < nb) g_blk[threadIdx.x] = sh[threadIdx.x] - v;
}

// ---- scan fixup + dinv finalize + hop-0 seed (fused) -------------------------
__global__ void __launch_bounds__(SCANB) k_scan3(const float* __restrict__ temp, int N, int E)
{
    int i = blockIdx.x * SCANB + threadIdx.x;
    if (i >= N) return;
    int val = g_off[i] + g_blk[i >> 10];
    g_off[i]    = val;
    g_cursor[i] = val;
    if (i == 0) g_off[N] = E;

    float d = rsqrtf((float)(g_deg[i] + 1));   // +1 self-loop
    g_dinv[i]   = d;
    float s     = g_s[i];
    g_hidden[i] = temp[0] * s;
    g_curwA[i]  = d * s;
}

// ---- scatter edges into CSC order -------------------------------------------
__global__ void __launch_bounds__(EBLK) k_scatter_vec(const int* __restrict__ row,
                                                      const int* __restrict__ col,
                                                      int E4, int rem)
{
    int t = blockIdx.x * blockDim.x + threadIdx.x;
    if (t < E4) {
        int4 r4 = reinterpret_cast<const int4*>(row)[t];
        int4 c4 = reinterpret_cast<const int4*>(col)[t];
        g_srow[atomicAdd(&g_cursor[c4.x], 1)] = r4.x;
        g_srow[atomicAdd(&g_cursor[c4.y], 1)] = r4.y;
        g_srow[atomicAdd(&g_cursor[c4.z], 1)] = r4.z;
        g_srow[atomicAdd(&g_cursor[c4.w], 1)] = r4.w;
    } else if (t - E4 < rem) {
        int e = 4 * E4 + (t - E4);
        g_srow[atomicAdd(&g_cursor[col[e]], 1)] = row[e];
    }
}
__global__ void __launch_bounds__(EBLK) k_scatter_sca(const int* __restrict__ row,
                                                      const int* __restrict__ col, int E)
{
    int e = blockIdx.x * blockDim.x + threadIdx.x;
    if (e < E) g_srow[atomicAdd(&g_cursor[col[e]], 1)] = row[e];
}

// ---- persistent propagation: all K hops, software grid barrier ---------------
// grid = 2 * #SMs, 1024-thread blocks, 2 blocks/SM (reg-capped to 32 by
// __launch_bounds__(1024,2)) -> 64 warps/SM, always fully co-resident.
__global__ void __launch_bounds__(PTHR, 2) k_prop(const float* __restrict__ temp,
                                                  const float* __restrict__ bfc,
                                                  float* __restrict__ out,
                                                  int N, int K)
{
    const int warpsPerBlk = PTHR / 32;
    const int nwarps = gridDim.x * warpsPerBlk;
    const int gw     = blockIdx.x * warpsPerBlk + (threadIdx.x >> 5);
    const int lane   = threadIdx.x & 31;

    // contiguous node range per warp (balanced); processed in <=32-node chunks
    const int npw    = (N + nwarps - 1) / nwarps;
    const int nodeLo = gw * npw;
    const int nodeHi = (nodeLo + npw < N) ? (nodeLo + npw) : N;

    unsigned target = 0;

    for (int k = 1; k <= K; k++) {
        const float gamma = __ldg(&temp[k]);
        const bool  last  = (k == K);
        // select ping-pong by parity (addresses are compile-time immediates)
        const float* curwIn  = (k & 1) ? g_curwA : g_curwB;
        float*       curwOut = (k & 1) ? g_curwB : g_curwA;

        for (int b = nodeLo; b < nodeHi; b += 32) {
            int  cnt = nodeHi - b; if (cnt > 32) cnt = 32;
            int  idx = b + lane;
            bool act = lane < cnt;

            // warp-coalesced node state (1 LDG each)
            int   myStart = act ? __ldg(&g_off[idx])     : 0;
            int   myNext  = act ? __ldg(&g_off[idx + 1]) : 0;
            float myDinv  = act ? g_dinv[idx]            : 0.0f;
            float myHid   = act ? g_hidden[idx]          : 0.0f;
            float mySelf  = act ? curwIn[idx]            : 0.0f;
            float mySum   = 0.0f;

            for (int j = 0; j < cnt; j++) {
                int s = __shfl_sync(0xFFFFFFFFu, myStart, j);
                int e = __shfl_sync(0xFFFFFFFFu, myNext,  j);

                float sum = 0.0f;
                for (int t = s + lane; t < e; t += 32)
                    sum += __ldg(&curwIn[__ldg(&g_srow[t])]);   // L1-cached gather

#pragma unroll
                for (int d = 16; d > 0; d >>= 1)
                    sum += __shfl_xor_sync(0xFFFFFFFFu, sum, d);

                if (lane == j) mySum = sum;
            }

            float cur = myDinv * (mySelf + mySum);
            float h   = fmaf(gamma, cur, myHid);
            if (act) {
                if (last) {
                    out[idx] = h + __ldg(&bfc[0]);      // coalesced
                } else {
                    g_hidden[idx] = h;                  // coalesced
                    curwOut[idx]  = myDinv * cur;       // coalesced
                }
            }
        }

        if (!last) {
            // grid barrier; gpu-scope fences emit CCTL.IVALL -> L1D coherent
            __syncthreads();
            if (threadIdx.x == 0) {
                __threadfence();                         // release (+IVALL)
                atomicAdd(&g_barrier, 1u);
                target += gridDim.x;
                while (*(volatile unsigned*)&g_barrier < target)
                    __nanosleep(32);
                __threadfence();                         // acquire (+IVALL)
            }
            __syncthreads();
        }
    }
}

// ---------------------------------------------------------------------------
extern "C" void kernel_launch(void* const* d_in, const int* in_sizes, int n_in,
                              void* d_out, int out_size)
{
    const float* x    = (const float*)d_in[0];
    const int*   ei   = (const int*)  d_in[1];
    const float* W1   = (const float*)d_in[2];
    const float* b1   = (const float*)d_in[3];
    const float* W2   = (const float*)d_in[4];
    const float* b2   = (const float*)d_in[5];
    const float* temp = (const float*)d_in[6];
    const float* Wfc  = (const float*)d_in[7];
    const float* bfc  = (const float*)d_in[8];
    float*       out  = (float*)d_out;

    int N = in_sizes[0];
    int E = in_sizes[1] / 2;
    int K = in_sizes[6] - 1;

    const int* row = ei;
    const int* col = ei + E;

    int nb    = (N + NBLK - 1) / NBLK;
    int nscan = (N + SCANB - 1) / SCANB;

    bool vec_ok = (E % 4 == 0);
    int  E4 = E >> 2, rem = E & 3;
    int  eb_vec = (E4 + rem + EBLK - 1) / EBLK;
    int  eb_sca = (E + EBLK - 1) / EBLK;

    // 2 blocks per SM (reg-capped) -> 64 warps/SM, fully co-resident
    int dev = 0, sms = 0;
    cudaGetDevice(&dev);
    cudaDeviceGetAttribute(&sms, cudaDevAttrMultiProcessorCount, dev);
    if (sms <= 0) sms = 148;

    k_mlp<<<nb, NBLK>>>(x, W1, b1, W2, b2, Wfc, N);

    if (vec_ok) k_hist_vec<<<eb_vec, EBLK>>>(col, E4, rem);
    else        k_hist_sca<<<eb_sca, EBLK>>>(col, E);
    k_scan1<<<nscan, SCANB>>>(N);
    k_scan2<<<1, MAXSB>>>(nscan);
    k_scan3<<<nscan, SCANB>>>(temp, N, E);
    if (vec_ok) k_scatter_vec<<<eb_vec, EBLK>>>(row, col, E4, rem);
    else        k_scatter_sca<<<eb_sca, EBLK>>>(row, col, E);

    k_prop<<<2 * sms, PTHR>>>(temp, bfc, out, N, K);
}